// round 1
// baseline (speedup 1.0000x reference)
#include <cuda_runtime.h>
#include <cuda_bf16.h>

#define N_BATCH 4096
#define T_SEQ   200
#define EMB     128

// ---------------- device scratch (no allocs allowed) ----------------
__device__ float g_pooled[N_BATCH * EMB];          // 2 MB
__device__ float g_wt1[128 * 512];                 // W1^T  [fin=128][fout=512]
__device__ float g_wt2[512 * 256];                 // W2^T  [512][256]
__device__ float g_wt3[256 * 128];                 // W3^T  [256][128]

// ---------------- 1) transpose weights: Wt[k][j] = W[j][k] ----------------
__global__ void transpose_weights(const float* __restrict__ W1,
                                  const float* __restrict__ W2,
                                  const float* __restrict__ W3) {
    int idx = blockIdx.x * blockDim.x + threadIdx.x;
    // W1: 512x128 -> 65536 ; W2: 256x512 -> 131072 ; W3: 128x256 -> 32768
    if (idx < 65536) {
        int k = idx >> 9, j = idx & 511;          // Wt1[k][j], fout=512
        g_wt1[idx] = W1[j * 128 + k];
    } else if (idx < 65536 + 131072) {
        int t = idx - 65536;
        int k = t >> 8, j = t & 255;              // Wt2[k][j], fout=256
        g_wt2[t] = W2[j * 512 + k];
    } else if (idx < 65536 + 131072 + 32768) {
        int t = idx - 65536 - 131072;
        int k = t >> 7, j = t & 127;              // Wt3[k][j], fout=128
        g_wt3[t] = W3[j * 256 + k];
    }
}

// ---------------- 2) pooling: one warp per sequence ----------------
__global__ void pool_kernel(const int* __restrict__ x,
                            const int* __restrict__ lengths,
                            const float* __restrict__ emb) {
    int gwarp = (blockIdx.x * blockDim.x + threadIdx.x) >> 5;
    int lane  = threadIdx.x & 31;
    if (gwarp >= N_BATCH) return;

    const int* xr = x + gwarp * T_SEQ;
    int len = lengths[gwarp];

    const float4* emb4 = (const float4*)emb;      // row = 32 float4
    float4 acc = make_float4(0.f, 0.f, 0.f, 0.f);

    int t = 0;
    for (; t + 4 <= len; t += 4) {
        int i0 = xr[t], i1 = xr[t + 1], i2 = xr[t + 2], i3 = xr[t + 3];
        float4 a = emb4[i0 * 32 + lane];
        float4 b = emb4[i1 * 32 + lane];
        float4 c = emb4[i2 * 32 + lane];
        float4 d = emb4[i3 * 32 + lane];
        acc.x += a.x + b.x + c.x + d.x;
        acc.y += a.y + b.y + c.y + d.y;
        acc.z += a.z + b.z + c.z + d.z;
        acc.w += a.w + b.w + c.w + d.w;
    }
    for (; t < len; ++t) {
        float4 a = emb4[xr[t] * 32 + lane];
        acc.x += a.x; acc.y += a.y; acc.z += a.z; acc.w += a.w;
    }
    float inv = 1.0f / (float)len;
    acc.x *= inv; acc.y *= inv; acc.z *= inv; acc.w *= inv;
    ((float4*)g_pooled)[gwarp * 32 + lane] = acc;
}

// ---------------- 3) fused MLP: 8 rows per block, 128 threads ----------------
#define RROWS 8

__global__ void __launch_bounds__(128) mlp_kernel(
        const float* __restrict__ b1,
        const float* __restrict__ b2,
        const float* __restrict__ b3,
        const float* __restrict__ W4,
        const float* __restrict__ b4,
        float* __restrict__ out) {
    __shared__ __align__(16) float sIn[RROWS * 128];
    __shared__ __align__(16) float s1 [RROWS * 512];
    __shared__ __align__(16) float s2 [RROWS * 256];
    __shared__ __align__(16) float s3 [RROWS * 128];

    int tid = threadIdx.x;
    int r0  = blockIdx.x * RROWS;

    // ---- stage pooled rows (coalesced float4) ----
    {
        const float4* src = (const float4*)(g_pooled + r0 * 128);
        float4* dst = (float4*)sIn;
        dst[tid]       = src[tid];
        dst[tid + 128] = src[tid + 128];
    }
    __syncthreads();

    // ---- layer 1: 128 -> 512, V=4 (j = 4*tid .. 4*tid+3) ----
    {
        const float4* Wt = (const float4*)g_wt1;   // row k: 128 float4 (512 f)
        float4 acc[RROWS];
        #pragma unroll
        for (int r = 0; r < RROWS; ++r) acc[r] = make_float4(0.f,0.f,0.f,0.f);
        #pragma unroll 4
        for (int k = 0; k < 128; ++k) {
            float4 w = Wt[k * 128 + tid];          // coalesced
            #pragma unroll
            for (int r = 0; r < RROWS; ++r) {
                float a = sIn[r * 128 + k];        // warp broadcast
                acc[r].x += a * w.x; acc[r].y += a * w.y;
                acc[r].z += a * w.z; acc[r].w += a * w.w;
            }
        }
        float4 bb = ((const float4*)b1)[tid];
        float4* s1v = (float4*)s1;
        #pragma unroll
        for (int r = 0; r < RROWS; ++r) {
            float4 v;
            v.x = fmaxf(acc[r].x + bb.x, 0.f);
            v.y = fmaxf(acc[r].y + bb.y, 0.f);
            v.z = fmaxf(acc[r].z + bb.z, 0.f);
            v.w = fmaxf(acc[r].w + bb.w, 0.f);
            s1v[r * 128 + tid] = v;
        }
    }
    __syncthreads();

    // ---- layer 2: 512 -> 256, V=2 (j = 2*tid, 2*tid+1) ----
    {
        const float2* Wt = (const float2*)g_wt2;   // row k: 128 float2 (256 f)
        float2 acc[RROWS];
        #pragma unroll
        for (int r = 0; r < RROWS; ++r) acc[r] = make_float2(0.f, 0.f);
        #pragma unroll 4
        for (int k = 0; k < 512; ++k) {
            float2 w = Wt[k * 128 + tid];          // coalesced
            #pragma unroll
            for (int r = 0; r < RROWS; ++r) {
                float a = s1[r * 512 + k];         // warp broadcast
                acc[r].x += a * w.x; acc[r].y += a * w.y;
            }
        }
        float2 bb = ((const float2*)b2)[tid];
        float2* s2v = (float2*)s2;
        #pragma unroll
        for (int r = 0; r < RROWS; ++r) {
            float2 v;
            v.x = fmaxf(acc[r].x + bb.x, 0.f);
            v.y = fmaxf(acc[r].y + bb.y, 0.f);
            s2v[r * 128 + tid] = v;
        }
    }
    __syncthreads();

    // ---- layer 3: 256 -> 128, V=1 (j = tid) ----
    {
        float acc[RROWS];
        #pragma unroll
        for (int r = 0; r < RROWS; ++r) acc[r] = 0.f;
        #pragma unroll 4
        for (int k = 0; k < 256; ++k) {
            float w = g_wt3[k * 128 + tid];        // coalesced
            #pragma unroll
            for (int r = 0; r < RROWS; ++r) {
                acc[r] += s2[r * 256 + k] * w;     // broadcast
            }
        }
        float bb = b3[tid];
        #pragma unroll
        for (int r = 0; r < RROWS; ++r)
            s3[r * 128 + tid] = fmaxf(acc[r] + bb, 0.f);
    }
    __syncthreads();

    // ---- layer 4: 128 -> 2 (threads 0..15: r = t>>1, j = t&1) ----
    if (tid < RROWS * 2) {
        int r = tid >> 1;
        int j = tid & 1;
        float acc = b4[j];
        #pragma unroll 4
        for (int k = 0; k < 128; ++k)
            acc += s3[r * 128 + k] * W4[j * 128 + k];
        out[(r0 + r) * 2 + j] = acc;
    }
}

// ---------------- launch ----------------
extern "C" void kernel_launch(void* const* d_in, const int* in_sizes, int n_in,
                              void* d_out, int out_size) {
    const int*   x       = (const int*)  d_in[0];
    const int*   lengths = (const int*)  d_in[1];
    const float* emb     = (const float*)d_in[2];
    const float* W1      = (const float*)d_in[3];
    const float* b1      = (const float*)d_in[4];
    const float* W2      = (const float*)d_in[5];
    const float* b2      = (const float*)d_in[6];
    const float* W3      = (const float*)d_in[7];
    const float* b3      = (const float*)d_in[8];
    const float* W4      = (const float*)d_in[9];
    const float* b4      = (const float*)d_in[10];
    float* out = (float*)d_out;

    // 1) transpose weights (229376 elems)
    transpose_weights<<<(229376 + 255) / 256, 256>>>(W1, W2, W3);

    // 2) pooling: 4096 warps -> 512 blocks of 256 threads
    pool_kernel<<<512, 256>>>(x, lengths, emb);

    // 3) fused MLP: 8 rows per block
    mlp_kernel<<<N_BATCH / RROWS, 128>>>(b1, b2, b3, W4, b4, out);
}